// round 16
// baseline (speedup 1.0000x reference)
#include <cuda_runtime.h>
#include <cstdint>

// ---------------------------------------------------------------------------
// Fused SSIM(11x11 gaussian) + Charbonnier + MSE — sum/diff + packed f32x2.
// Champion R7 structure byte-for-byte (32x32 tile, 256 thr, scalar interleaved
// halo load, CG=8/RG=8 input-stationary FFMA2 conv, LDS.64/STS.64,
// conflict-free odd strides) + ONE change: __launch_bounds__(256, 5) caps
// registers at 51 so 5 CTAs become resident per SM (was reg-limited at 4),
// raising resident warps 32 -> 40 to lift the 65% issue ceiling.
// ---------------------------------------------------------------------------

#define WIN   11
#define RAD   5
#define TX    32
#define TY    32
#define HX    42
#define HY    42
#define SR2   43            // raw row stride in ull units
#define SH2   33            // intermediate row stride in ull units
#define IMG_H 512
#define IMG_W 512
#define NTHREADS 256
#define CG    8             // cols per horizontal task: 42*4 = 168 tasks
#define RG    8             // rows per vertical thread: 32*4 = 128 tasks

typedef unsigned long long ull;

__device__ __forceinline__ ull pk(float a, float b) {
    return ((ull)__float_as_uint(b) << 32) | (ull)__float_as_uint(a);
}
__device__ __forceinline__ float flo(ull v) { return __uint_as_float((unsigned)v); }
__device__ __forceinline__ float fhi(ull v) { return __uint_as_float((unsigned)(v >> 32)); }

__device__ __forceinline__ ull fma2(ull a, ull b, ull c) {
    ull d;
    asm("fma.rn.f32x2 %0, %1, %2, %3;" : "=l"(d) : "l"(a), "l"(b), "l"(c));
    return d;
}
__device__ __forceinline__ ull mul2(ull a, ull b) {
    ull d;
    asm("mul.rn.f32x2 %0, %1, %2;" : "=l"(d) : "l"(a), "l"(b));
    return d;
}
__device__ __forceinline__ float sqrt_approx(float x) {
    float r;
    asm("sqrt.approx.f32 %0, %1;" : "=f"(r) : "f"(x));
    return r;
}

__device__ __forceinline__ float cw(int i) {
    constexpr float W[WIN] = {
        0.00102838f, 0.00759876f, 0.03600077f, 0.10936069f, 0.21300553f,
        0.26601172f,
        0.21300553f, 0.10936069f, 0.03600077f, 0.00759876f, 0.00102838f };
    return W[i];
}

__global__ __launch_bounds__(NTHREADS, 5)
void ssim_charb_mse_kernel(const float* __restrict__ pred,
                           const float* __restrict__ targ,
                           float* __restrict__ out)
{
    __shared__ ull s_raw[HY * SR2];   // 14448 B : packed (s, d)
    __shared__ ull h_a[HY * SH2];     // 11088 B : packed (G_h s,   G_h d)
    __shared__ ull h_b[HY * SH2];     // 11088 B : packed (G_h s^2, G_h d^2)

    const int plane = blockIdx.z;
    const int x0 = blockIdx.x * TX;
    const int y0 = blockIdx.y * TY;
    const size_t pbase = (size_t)plane * IMG_H * IMG_W;
    const float* __restrict__ p = pred + pbase;
    const float* __restrict__ t = targ + pbase;
    float* __restrict__ o = out + pbase;

    const int tid = threadIdx.x;

    // ---- 1. halo load: pack (s,d); interior CTAs skip bounds checks ----
    const bool interior = (x0 >= RAD) & (x0 + TX + RAD <= IMG_W) &
                          (y0 >= RAD) & (y0 + TY + RAD <= IMG_H);
    if (interior) {
        const int gb = (y0 - RAD) * IMG_W + (x0 - RAD);
        #pragma unroll 1
        for (int idx = tid; idx < HY * HX; idx += NTHREADS) {
            const int r = idx / HX;
            const int c = idx - r * HX;
            const int g = gb + r * IMG_W + c;
            const float pv = p[g];
            const float tv = t[g];
            s_raw[r * SR2 + c] = pk(pv + tv, pv - tv);
        }
    } else {
        #pragma unroll 1
        for (int idx = tid; idx < HY * HX; idx += NTHREADS) {
            const int r = idx / HX;
            const int c = idx - r * HX;
            const int gy = y0 + r - RAD;
            const int gx = x0 + c - RAD;
            float sv = 0.f, dv = 0.f;
            if ((unsigned)gy < (unsigned)IMG_H && (unsigned)gx < (unsigned)IMG_W) {
                const int g = gy * IMG_W + gx;
                const float pv = p[g];
                const float tv = t[g];
                sv = pv + tv;
                dv = pv - tv;
            }
            s_raw[r * SR2 + c] = pk(sv, dv);
        }
    }
    __syncthreads();

    // ---- 2. horizontal pass: 168 tasks (42 rows x 4 col-groups), CG=8 ----
    if (tid < HY * (TX / CG)) {                // 168 < 256: one round
        const int g  = tid / HY;               // col group 0..3
        const int r  = tid - g * HY;           // row 0..41 (consecutive per lane)
        const int c0 = g * CG;
        const int rb = r * SR2 + c0;

        ull m1[CG], m2[CG];
        #pragma unroll
        for (int k = 0; k < CG; ++k) { m1[k] = 0ULL; m2[k] = 0ULL; }

        #pragma unroll
        for (int i = 0; i < CG + WIN - 1; ++i) {          // 18 inputs
            const ull v  = s_raw[rb + i];                 // (s, d)
            const ull v2 = mul2(v, v);                    // (s^2, d^2)
            #pragma unroll
            for (int k = 0; k < CG; ++k) {
                const int tap = i - k;
                if (tap >= 0 && tap < WIN) {
                    const ull w = pk(cw(tap), cw(tap));
                    m1[k] = fma2(w, v,  m1[k]);
                    m2[k] = fma2(w, v2, m2[k]);
                }
            }
        }
        const int hb = r * SH2 + c0;
        #pragma unroll
        for (int k = 0; k < CG; ++k) {
            h_a[hb + k] = m1[k];
            h_b[hb + k] = m2[k];
        }
    }
    __syncthreads();

    // ---- 3. vertical pass + loss: 128 tasks, 8-row column strips ----
    if (tid < TX * (TY / RG)) {                // 128 < 256: one round
        const int c    = tid & 31;
        const int strip= tid >> 5;             // 0..3
        const int r0   = strip * RG;

        ull E1[RG], E2[RG];
        #pragma unroll
        for (int k = 0; k < RG; ++k) { E1[k] = 0ULL; E2[k] = 0ULL; }

        #pragma unroll
        for (int j = 0; j < RG + WIN - 1; ++j) {          // 18 h-rows
            const int hb = (r0 + j) * SH2 + c;
            const ull va = h_a[hb];
            const ull vb = h_b[hb];
            #pragma unroll
            for (int k = 0; k < RG; ++k) {
                const int tap = j - k;
                if (tap >= 0 && tap < WIN) {
                    const ull w = pk(cw(tap), cw(tap));
                    E1[k] = fma2(w, va, E1[k]);
                    E2[k] = fma2(w, vb, E2[k]);
                }
            }
        }

        const float C1 = 0.0001f;       // (0.01)^2
        const float C2 = 0.0009f;       // (0.03)^2
        const float EPS2 = 1e-12f;      // (1e-6)^2

        #pragma unroll
        for (int k = 0; k < RG; ++k) {
            const float Es  = flo(E1[k]), Ed  = fhi(E1[k]);
            const float Es2 = flo(E2[k]), Ed2 = fhi(E2[k]);

            const float mus2 = Es * Es;              // (mx+my)^2
            const float mud2 = Ed * Ed;              // (mx-my)^2
            const float dif  = 0.5f * (mus2 - mud2); // 2 mx my
            const float sum  = 0.5f * (mus2 + mud2); // mx^2 + my^2

            const float A1 = dif + C1;
            const float B1 = sum + C1;
            const float A2 = 0.5f * (Es2 - Ed2) - dif + C2;
            const float B2 = 0.5f * (Es2 + Ed2) - sum + C2;
            const float ssim = __fdividef(A1 * A2, B1 * B2);

            const float dcen = fhi(s_raw[(r0 + k + RAD) * SR2 + (c + RAD)]);
            const float d2c  = dcen * dcen;
            const float charb = sqrt_approx(d2c + EPS2);
            const float loss = 0.3f * charb + 2.0f * d2c + 0.6f * (1.f - ssim);

            o[(y0 + r0 + k) * IMG_W + (x0 + c)] = loss;
        }
    }
}

extern "C" void kernel_launch(void* const* d_in, const int* in_sizes, int n_in,
                              void* d_out, int out_size)
{
    const float* pred = (const float*)d_in[0];
    const float* targ = (const float*)d_in[1];
    float* out = (float*)d_out;

    const int planes = out_size / (IMG_H * IMG_W);   // 48
    dim3 grid(IMG_W / TX, IMG_H / TY, planes);       // 16,16,48
    dim3 block(NTHREADS);
    ssim_charb_mse_kernel<<<grid, block>>>(pred, targ, out);
}

// round 17
// speedup vs baseline: 1.3861x; 1.3861x over previous
#include <cuda_runtime.h>
#include <cstdint>

// ---------------------------------------------------------------------------
// Fused SSIM(11x11 gaussian) + Charbonnier + MSE — sum/diff + packed f32x2.
// Champion R7 structure (32x32 tile, 256 thr, static smem, CG=8/RG=8
// input-stationary FFMA2 conv, LDS.64/STS.64, conflict-free odd strides)
// with two local trims:
//   (1) div-free phase-1 indexing (column-stationary, strided rows)
//   (2) epilogue scale factors folded into horizontal weights:
//       chanA taps *= 1/sqrt(2), chanB taps *= 1/2  ->  mus2 = Es'^2 etc.
// ---------------------------------------------------------------------------

#define WIN   11
#define RAD   5
#define TX    32
#define TY    32
#define HX    42
#define HY    42
#define SR2   43            // raw row stride in ull units
#define SH2   33            // intermediate row stride in ull units
#define IMG_H 512
#define IMG_W 512
#define NTHREADS 256
#define CG    8             // cols per horizontal task: 42*4 = 168 tasks
#define RG    8             // rows per vertical thread: 32*4 = 128 tasks

typedef unsigned long long ull;

__device__ __forceinline__ ull pk(float a, float b) {
    return ((ull)__float_as_uint(b) << 32) | (ull)__float_as_uint(a);
}
__device__ __forceinline__ float flo(ull v) { return __uint_as_float((unsigned)v); }
__device__ __forceinline__ float fhi(ull v) { return __uint_as_float((unsigned)(v >> 32)); }

__device__ __forceinline__ ull fma2(ull a, ull b, ull c) {
    ull d;
    asm("fma.rn.f32x2 %0, %1, %2, %3;" : "=l"(d) : "l"(a), "l"(b), "l"(c));
    return d;
}
__device__ __forceinline__ ull mul2(ull a, ull b) {
    ull d;
    asm("mul.rn.f32x2 %0, %1, %2;" : "=l"(d) : "l"(a), "l"(b));
    return d;
}
__device__ __forceinline__ float sqrt_approx(float x) {
    float r;
    asm("sqrt.approx.f32 %0, %1;" : "=f"(r) : "f"(x));
    return r;
}

// base gaussian weights (sigma=1.5, win=11)
__device__ __forceinline__ float cw(int i) {
    constexpr float W[WIN] = {
        0.00102838f, 0.00759876f, 0.03600077f, 0.10936069f, 0.21300553f,
        0.26601172f,
        0.21300553f, 0.10936069f, 0.03600077f, 0.00759876f, 0.00102838f };
    return W[i];
}
// horizontal chanA weights: w * (1/sqrt(2))  -> total scale 1/sqrt(2)
__device__ __forceinline__ float cwA(int i) { return cw(i) * 0.70710678118654752f; }
// horizontal chanB weights: w * 0.5          -> total scale 1/2
__device__ __forceinline__ float cwB(int i) { return cw(i) * 0.5f; }

__global__ __launch_bounds__(NTHREADS)
void ssim_charb_mse_kernel(const float* __restrict__ pred,
                           const float* __restrict__ targ,
                           float* __restrict__ out)
{
    __shared__ ull s_raw[HY * SR2];   // 14448 B : packed (s, d)
    __shared__ ull h_a[HY * SH2];     // 11088 B : packed (G_h s /√2, G_h d /√2)
    __shared__ ull h_b[HY * SH2];     // 11088 B : packed (G_h s^2 /2, G_h d^2 /2)

    const int plane = blockIdx.z;
    const int x0 = blockIdx.x * TX;
    const int y0 = blockIdx.y * TY;
    const size_t pbase = (size_t)plane * IMG_H * IMG_W;
    const float* __restrict__ p = pred + pbase;
    const float* __restrict__ t = targ + pbase;
    float* __restrict__ o = out + pbase;

    const int tid = threadIdx.x;

    // ---- 1. halo load (div-free): thread = (col c, row-block rb), 7 rows ----
    if (tid < 6 * HX) {                        // 252 threads used
        const int c  = tid % HX;               // 0..41 (consecutive per lane)
        const int rb = tid / HX;               // 0..5, rows rb*7 .. rb*7+6
        const bool interior = (x0 >= RAD) & (x0 + TX + RAD <= IMG_W) &
                              (y0 >= RAD) & (y0 + TY + RAD <= IMG_H);
        int saddr = (rb * 7) * SR2 + c;
        if (interior) {
            const float* pg = p + (y0 - RAD + rb * 7) * IMG_W + (x0 - RAD + c);
            const float* tg = t + (y0 - RAD + rb * 7) * IMG_W + (x0 - RAD + c);
            #pragma unroll
            for (int k = 0; k < 7; ++k) {
                const float pv = pg[k * IMG_W];
                const float tv = tg[k * IMG_W];
                s_raw[saddr] = pk(pv + tv, pv - tv);
                saddr += SR2;
            }
        } else {
            const int gx = x0 + c - RAD;
            const bool xok = (unsigned)gx < (unsigned)IMG_W;
            int gy = y0 + rb * 7 - RAD;
            #pragma unroll
            for (int k = 0; k < 7; ++k) {
                float sv = 0.f, dv = 0.f;
                if (xok && (unsigned)gy < (unsigned)IMG_H) {
                    const int g = gy * IMG_W + gx;
                    const float pv = p[g];
                    const float tv = t[g];
                    sv = pv + tv;
                    dv = pv - tv;
                }
                s_raw[saddr] = pk(sv, dv);
                saddr += SR2;
                ++gy;
            }
        }
    }
    __syncthreads();

    // ---- 2. horizontal pass: 168 tasks (42 rows x 4 col-groups), CG=8 ----
    if (tid < HY * (TX / CG)) {                // 168 < 256: one round
        const int g  = tid / HY;               // col group 0..3
        const int r  = tid - g * HY;           // row 0..41 (consecutive per lane)
        const int c0 = g * CG;
        const int rb = r * SR2 + c0;

        ull m1[CG], m2[CG];
        #pragma unroll
        for (int k = 0; k < CG; ++k) { m1[k] = 0ULL; m2[k] = 0ULL; }

        #pragma unroll
        for (int i = 0; i < CG + WIN - 1; ++i) {          // 18 inputs
            const ull v  = s_raw[rb + i];                 // (s, d)
            const ull v2 = mul2(v, v);                    // (s^2, d^2)
            #pragma unroll
            for (int k = 0; k < CG; ++k) {
                const int tap = i - k;
                if (tap >= 0 && tap < WIN) {
                    m1[k] = fma2(pk(cwA(tap), cwA(tap)), v,  m1[k]);
                    m2[k] = fma2(pk(cwB(tap), cwB(tap)), v2, m2[k]);
                }
            }
        }
        const int hb = r * SH2 + c0;
        #pragma unroll
        for (int k = 0; k < CG; ++k) {
            h_a[hb + k] = m1[k];
            h_b[hb + k] = m2[k];
        }
    }
    __syncthreads();

    // ---- 3. vertical pass + loss: 128 tasks, 8-row column strips ----
    if (tid < TX * (TY / RG)) {                // 128 < 256: one round
        const int c    = tid & 31;
        const int strip= tid >> 5;             // 0..3
        const int r0   = strip * RG;

        ull E1[RG], E2[RG];
        #pragma unroll
        for (int k = 0; k < RG; ++k) { E1[k] = 0ULL; E2[k] = 0ULL; }

        #pragma unroll
        for (int j = 0; j < RG + WIN - 1; ++j) {          // 18 h-rows
            const int hb = (r0 + j) * SH2 + c;
            const ull va = h_a[hb];
            const ull vb = h_b[hb];
            #pragma unroll
            for (int k = 0; k < RG; ++k) {
                const int tap = j - k;
                if (tap >= 0 && tap < WIN) {
                    const ull w = pk(cw(tap), cw(tap));
                    E1[k] = fma2(w, va, E1[k]);
                    E2[k] = fma2(w, vb, E2[k]);
                }
            }
        }

        const float C1 = 0.0001f;       // (0.01)^2
        const float C2 = 0.0009f;       // (0.03)^2
        const float EPS2 = 1e-12f;      // (1e-6)^2

        #pragma unroll
        for (int k = 0; k < RG; ++k) {
            // E1 = (G(s)/√2, G(d)/√2);  E2 = (G(s^2)/2, G(d^2)/2)
            const float Es  = flo(E1[k]), Ed  = fhi(E1[k]);
            const float Es2 = flo(E2[k]), Ed2 = fhi(E2[k]);

            const float mus2 = Es * Es;            // 0.5 (mx+my)^2
            const float mud2 = Ed * Ed;            // 0.5 (mx-my)^2
            const float dif  = mus2 - mud2;        // 2 mx my
            const float sum  = mus2 + mud2;        // mx^2 + my^2

            const float A1s = fmaf(0.6f, dif, 0.6f * C1);   // 0.6 * A1
            const float B1  = sum + C1;
            const float A2  = (Es2 - Ed2) - dif + C2;       // 2 sigma_xy + C2
            const float B2  = (Es2 + Ed2) - sum + C2;       // sxx+syy + C2
            const float ssim6 = __fdividef(A1s * A2, B1 * B2);  // 0.6*ssim

            const float dcen = fhi(s_raw[(r0 + k + RAD) * SR2 + (c + RAD)]);
            const float d2c  = dcen * dcen;
            const float charb = sqrt_approx(d2c + EPS2);
            const float loss = fmaf(0.3f, charb, fmaf(2.0f, d2c, 0.6f)) - ssim6;

            o[(y0 + r0 + k) * IMG_W + (x0 + c)] = loss;
        }
    }
}

extern "C" void kernel_launch(void* const* d_in, const int* in_sizes, int n_in,
                              void* d_out, int out_size)
{
    const float* pred = (const float*)d_in[0];
    const float* targ = (const float*)d_in[1];
    float* out = (float*)d_out;

    const int planes = out_size / (IMG_H * IMG_W);   // 48
    dim3 grid(IMG_W / TX, IMG_H / TY, planes);       // 16,16,48
    dim3 block(NTHREADS);
    ssim_charb_mse_kernel<<<grid, block>>>(pred, targ, out);
}